// round 4
// baseline (speedup 1.0000x reference)
#include <cuda_runtime.h>
#include <math.h>
#include <stdint.h>

// Problem constants
#define N_POS    65536
#define N_E      2048
#define C_DIM    64
#define PLANE    4096
#define ZQ_ELEMS 4194304
#define TAU      0.03f

// Persistent device scratch
__device__ int                g_idx[N_POS];
__device__ int                g_hist[N_E];
__device__ float              g_loss;
__device__ int                g_nflag;
__device__ int                g_flag[N_POS];
__device__ unsigned long long g_fb_key[N_POS];

// ---------------------------------------------------------------------------
// helpers
// ---------------------------------------------------------------------------
__device__ __forceinline__ unsigned int ordered_u32(float f) {
    unsigned int u = __float_as_uint(f);
    return (u & 0x80000000u) ? ~u : (u | 0x80000000u);
}
__device__ __forceinline__ unsigned long long dup2(float f) {
    unsigned long long d;
    unsigned int b = __float_as_uint(f);
    asm("mov.b64 %0, {%1,%1};" : "=l"(d) : "r"(b));
    return d;
}
#define FFMA2(acc, a, b) \
    asm("fma.rn.f32x2 %0, %1, %2, %0;" : "+l"(acc) : "l"(a), "l"(b))
#define FMUL2(dst, a, b) \
    asm("mul.rn.f32x2 %0, %1, %2;" : "=l"(dst) : "l"(a), "l"(b))

// ---------------------------------------------------------------------------
// Kernel 0: clear accumulators
// ---------------------------------------------------------------------------
__global__ void vq_init_kernel() {
    int gt = blockIdx.x * 256 + threadIdx.x;
    if (gt < N_POS) g_fb_key[gt] = 0ull;
    if (gt < N_E)   g_hist[gt]   = 0;
    if (gt == 0) { g_loss = 0.0f; g_nflag = 0; }
}

// ---------------------------------------------------------------------------
// Kernel 1: FFMA2 (packed f32x2) argmax GEMM.
// Block = 128 positions x 2048 codes, 256 threads.
// tx = tid&15 owns 8 positions (4 packed pairs); ty = tid>>4 owns 8 codes.
// smem: z_t[64][128] fp32 (32KB) + cb_d[64][128] u64 code-duplicated (64KB).
// Top-2 tracked as index-packed floats: low 11 mantissa bits = 2047-idx.
// ---------------------------------------------------------------------------
extern __shared__ float dyn_smem[];

__global__ void __launch_bounds__(256, 2)
vq_argmax_kernel(const float* __restrict__ z, const float* __restrict__ cb) {
    float*              z_t  = dyn_smem;                                   // [64][128]
    unsigned long long* cb_d = (unsigned long long*)(dyn_smem + 8192);     // [64][128]

    const int tid = threadIdx.x;
    const int tx  = tid & 15;      // position group (8 positions)
    const int ty  = tid >> 4;      // code group     (8 codes)

    const int n0 = blockIdx.x * 128;
    const int b  = n0 >> 12;
    const int p0 = n0 & 4095;
    const float* zb = z + (size_t)b * (C_DIM * PLANE) + p0;

    // ---- load z tile: z_t[c][pos], coalesced float4 ----
    #pragma unroll
    for (int k = 0; k < 8; k++) {
        int fid = tid + k * 256;               // 2048 float4 units
        int c   = fid >> 5;
        int pg  = fid & 31;
        float4 v = *(const float4*)(zb + c * PLANE + pg * 4);
        *(float4*)&z_t[c * 128 + pg * 4] = v;
    }

    float fv1[8], fv2[8];
    #pragma unroll
    for (int s = 0; s < 8; s++) { fv1[s] = -1e30f; fv2[s] = -1e30f; }

    for (int chunk = 0; chunk < 16; chunk++) {
        __syncthreads();
        // ---- load 128-code chunk duplicated: cb_d[c][code] = (v,v) ----
        #pragma unroll
        for (int k = 0; k < 8; k++) {
            int fid  = tid + k * 256;
            int code = fid & 127;
            int c4   = fid >> 7;               // 0..15
            float4 v = *(const float4*)(cb + (size_t)(chunk * 128 + code) * C_DIM + c4 * 4);
            cb_d[(c4 * 4 + 0) * 128 + code] = dup2(v.x);
            cb_d[(c4 * 4 + 1) * 128 + code] = dup2(v.y);
            cb_d[(c4 * 4 + 2) * 128 + code] = dup2(v.z);
            cb_d[(c4 * 4 + 3) * 128 + code] = dup2(v.w);
        }
        __syncthreads();

        unsigned long long acc[4][8];

        // ---- c = 0 peeled (mul instead of fma: zero-init for free) ----
        {
            ulonglong2 a01 = *(ulonglong2*)&z_t[tx * 8];
            ulonglong2 a23 = *(ulonglong2*)&z_t[tx * 8 + 4];
            unsigned long long av[4] = { a01.x, a01.y, a23.x, a23.y };
            ulonglong2 b01 = *(ulonglong2*)&cb_d[ty * 8];
            ulonglong2 b23 = *(ulonglong2*)&cb_d[ty * 8 + 2];
            ulonglong2 b45 = *(ulonglong2*)&cb_d[ty * 8 + 4];
            ulonglong2 b67 = *(ulonglong2*)&cb_d[ty * 8 + 6];
            unsigned long long bv[8] = { b01.x, b01.y, b23.x, b23.y,
                                         b45.x, b45.y, b67.x, b67.y };
            #pragma unroll
            for (int p = 0; p < 4; p++)
                #pragma unroll
                for (int j = 0; j < 8; j++)
                    FMUL2(acc[p][j], av[p], bv[j]);
        }

        #pragma unroll 9
        for (int c = 1; c < C_DIM; c++) {
            ulonglong2 a01 = *(ulonglong2*)&z_t[c * 128 + tx * 8];
            ulonglong2 a23 = *(ulonglong2*)&z_t[c * 128 + tx * 8 + 4];
            unsigned long long av[4] = { a01.x, a01.y, a23.x, a23.y };
            ulonglong2 b01 = *(ulonglong2*)&cb_d[c * 128 + ty * 8];
            ulonglong2 b23 = *(ulonglong2*)&cb_d[c * 128 + ty * 8 + 2];
            ulonglong2 b45 = *(ulonglong2*)&cb_d[c * 128 + ty * 8 + 4];
            ulonglong2 b67 = *(ulonglong2*)&cb_d[c * 128 + ty * 8 + 6];
            unsigned long long bv[8] = { b01.x, b01.y, b23.x, b23.y,
                                         b45.x, b45.y, b67.x, b67.y };
            #pragma unroll
            for (int p = 0; p < 4; p++)
                #pragma unroll
                for (int j = 0; j < 8; j++)
                    FFMA2(acc[p][j], av[p], bv[j]);
        }

        // ---- chunk epilogue: index-packed top-2 update ----
        #pragma unroll
        for (int j = 0; j < 8; j++) {
            const unsigned int idxb = (unsigned int)(2047 - (chunk * 128 + ty * 8 + j));
            #pragma unroll
            for (int p = 0; p < 4; p++) {
                unsigned int lo = (unsigned int)acc[p][j];
                unsigned int hi = (unsigned int)(acc[p][j] >> 32);
                float pfl = __uint_as_float((lo & 0xFFFFF800u) | idxb);
                float pfh = __uint_as_float((hi & 0xFFFFF800u) | idxb);
                const int s0 = 2 * p, s1 = 2 * p + 1;
                fv2[s0] = fmaxf(fv2[s0], fminf(fv1[s0], pfl));
                fv1[s0] = fmaxf(fv1[s0], pfl);
                fv2[s1] = fmaxf(fv2[s1], fminf(fv1[s1], pfh));
                fv1[s1] = fmaxf(fv1[s1], pfh);
            }
        }
    }

    // ---- cross-thread merge over the 16 code groups (reuse z_t smem) ----
    __syncthreads();
    float* s1 = dyn_smem;            // [16][128]
    float* s2 = dyn_smem + 2048;     // [16][128]
    #pragma unroll
    for (int s = 0; s < 8; s++) {
        s1[ty * 128 + tx * 8 + s] = fv1[s];
        s2[ty * 128 + tx * 8 + s] = fv2[s];
    }
    __syncthreads();
    if (tid < 128) {
        float V1 = -1e30f, V2 = -1e30f;
        #pragma unroll
        for (int t = 0; t < 16; t++) {
            float f1 = s1[t * 128 + tid];
            float f2 = s2[t * 128 + tid];
            V2 = fmaxf(V2, fminf(V1, f1));
            V1 = fmaxf(V1, f1);
            V2 = fmaxf(V2, f2);
        }
        unsigned int u1 = __float_as_uint(V1);
        int idx = 2047 - (int)(u1 & 0x7FFu);
        float v1m = __uint_as_float(u1 & 0xFFFFF800u);
        float v2m = __uint_as_float(__float_as_uint(V2) & 0xFFFFF800u);
        g_idx[n0 + tid] = idx;
        if (v1m - v2m < TAU) {
            int slot = atomicAdd(&g_nflag, 1);
            g_flag[slot] = n0 + tid;
        }
    }
}

// ---------------------------------------------------------------------------
// Kernel 2: exact fp32 rescue for flagged positions (keyed by position)
// ---------------------------------------------------------------------------
#define FB_GRID_Y 128

__global__ void __launch_bounds__(256)
vq_fallback_kernel(const float* __restrict__ z, const float* __restrict__ cb) {
    __shared__ float z_fs[16][68];
    const int nf = g_nflag;
    const int t  = threadIdx.x;
    const int p  = t >> 4;
    const int l  = t & 15;

    for (int gidx = blockIdx.y; gidx * 16 < nf; gidx += FB_GRID_Y) {
        const int fi = gidx * 16 + p;
        const bool valid = (fi < nf);
        const int pos = valid ? g_flag[fi] : 0;
        const int b  = pos >> 12;
        const int pp = pos & 4095;

        __syncthreads();
        #pragma unroll
        for (int j = 0; j < 4; j++) {
            int c = l * 4 + j;
            z_fs[p][c] = z[(size_t)b * (C_DIM * PLANE) + (size_t)c * PLANE + pp];
        }
        __syncthreads();

        float4 az[16];
        #pragma unroll
        for (int k4 = 0; k4 < 16; k4++) az[k4] = *(float4*)&z_fs[p][k4 * 4];

        float bv = -1e30f;
        int   bi = 0;
        const int cbase = blockIdx.x * 256 + l * 16;
        #pragma unroll 4
        for (int j = 0; j < 16; j++) {
            const int code = cbase + j;
            const float4* cr = (const float4*)(cb + (size_t)code * C_DIM);
            float acc = 0.0f;
            #pragma unroll
            for (int k4 = 0; k4 < 16; k4++) {
                float4 cv = cr[k4];
                acc = fmaf(az[k4].x, cv.x, acc);
                acc = fmaf(az[k4].y, cv.y, acc);
                acc = fmaf(az[k4].z, cv.z, acc);
                acc = fmaf(az[k4].w, cv.w, acc);
            }
            if (acc > bv) { bv = acc; bi = code; }
        }
        #pragma unroll
        for (int off = 1; off <= 8; off <<= 1) {
            float ov = __shfl_xor_sync(0xffffffffu, bv, off);
            int   oi = __shfl_xor_sync(0xffffffffu, bi, off);
            if (ov > bv || (ov == bv && oi < bi)) { bv = ov; bi = oi; }
        }
        if (l == 0 && valid) {
            unsigned long long key =
                ((unsigned long long)ordered_u32(bv) << 32) |
                (unsigned long long)(unsigned int)(2047 - bi);
            atomicMax(&g_fb_key[pos], key);
        }
    }
}

// ---------------------------------------------------------------------------
// Kernel 3: gather + loss + histogram + indices (applies rescue keys inline)
// ---------------------------------------------------------------------------
__global__ void __launch_bounds__(256)
vq_gather_kernel(const float* __restrict__ z, const float* __restrict__ cb,
                 float* __restrict__ out_zq, float* __restrict__ out_idx_f) {
    __shared__ int   sh_hist[N_E];
    __shared__ float sh_red[8];

    const int tid = threadIdx.x;
    #pragma unroll
    for (int k = tid; k < N_E; k += 256) sh_hist[k] = 0;
    __syncthreads();

    const int n = blockIdx.x * 256 + tid;
    unsigned long long key = g_fb_key[n];
    int e = g_idx[n];
    if (key) e = 2047 - (int)(unsigned int)(key & 0xffffffffull);

    const int b = n >> 12;
    const int p = n & 4095;
    const float*  zb = z      + (size_t)b * (C_DIM * PLANE) + p;
    float*        ob = out_zq + (size_t)b * (C_DIM * PLANE) + p;
    const float4* cr = (const float4*)(cb + (size_t)e * C_DIM);

    float s = 0.0f;
    #pragma unroll
    for (int c4 = 0; c4 < 16; c4++) {
        float4 q = cr[c4];
        const float* zp0 = zb + (c4 * 4) * PLANE;
        float*       op0 = ob + (c4 * 4) * PLANE;
        float d;
        d = q.x - zp0[0];          s = fmaf(d, d, s); op0[0]          = q.x;
        d = q.y - zp0[PLANE];      s = fmaf(d, d, s); op0[PLANE]      = q.y;
        d = q.z - zp0[2 * PLANE];  s = fmaf(d, d, s); op0[2 * PLANE]  = q.z;
        d = q.w - zp0[3 * PLANE];  s = fmaf(d, d, s); op0[3 * PLANE]  = q.w;
    }

    out_idx_f[n] = (float)e;
    atomicAdd(&sh_hist[e], 1);

    #pragma unroll
    for (int off = 16; off; off >>= 1) s += __shfl_xor_sync(0xffffffffu, s, off);
    if ((tid & 31) == 0) sh_red[tid >> 5] = s;
    __syncthreads();
    if (tid == 0) {
        float t = 0.0f;
        #pragma unroll
        for (int w = 0; w < 8; w++) t += sh_red[w];
        atomicAdd(&g_loss, t);
    }
    #pragma unroll
    for (int k = tid; k < N_E; k += 256) {
        int v = sh_hist[k];
        if (v) atomicAdd(&g_hist[k], v);
    }
}

// ---------------------------------------------------------------------------
// Kernel 4: finalize loss + perplexity
// ---------------------------------------------------------------------------
__global__ void vq_finalize_kernel(float* __restrict__ out) {
    __shared__ float red[256];
    const int tid = threadIdx.x;
    float part = 0.0f;
    #pragma unroll
    for (int k = tid; k < N_E; k += 256) {
        float em = (float)g_hist[k] * (1.0f / 65536.0f);
        part += em * logf(em + 1e-10f);
    }
    red[tid] = part;
    __syncthreads();
    for (int s = 128; s; s >>= 1) {
        if (tid < s) red[tid] += red[tid + s];
        __syncthreads();
    }
    if (tid == 0) {
        out[ZQ_ELEMS]     = g_loss * (1.25f / (float)ZQ_ELEMS);
        out[ZQ_ELEMS + 1] = expf(-red[0]);
    }
}

// ---------------------------------------------------------------------------
// Launch chain. Output: [ z_q | loss | perplexity | indices ]
// ---------------------------------------------------------------------------
#define SMEM_ARG ((8192 + 16384) * 4)   // 96 KB

extern "C" void kernel_launch(void* const* d_in, const int* in_sizes, int n_in,
                              void* d_out, int out_size) {
    const float* z  = (const float*)d_in[0];
    const float* cb = (const float*)d_in[1];
    float* out = (float*)d_out;

    cudaFuncSetAttribute(vq_argmax_kernel,
                         cudaFuncAttributeMaxDynamicSharedMemorySize, SMEM_ARG);

    vq_init_kernel<<<256, 256>>>();
    vq_argmax_kernel<<<N_POS / 128, 256, SMEM_ARG>>>(z, cb);
    vq_fallback_kernel<<<dim3(8, FB_GRID_Y), 256>>>(z, cb);
    vq_gather_kernel<<<N_POS / 256, 256>>>(z, cb, out, out + ZQ_ELEMS + 2);
    vq_finalize_kernel<<<1, 256>>>(out);
    (void)in_sizes; (void)n_in; (void)out_size;
}